// round 2
// baseline (speedup 1.0000x reference)
#include <cuda_runtime.h>
#include <math.h>

// ---- problem constants (fixed shapes) ----
#define PPATCH 7
#define NPK   10
#define WINSZ 20
#define LLEN  14            // WIN - P + 1
#define EMB   128
#define HH    160
#define WW    160
#define NBC   32            // B*C = 4*8
#define NGRID 36            // positions per axis
#define NPOS  (NGRID*NGRID) // 1296
#define NUNIT (NPOS*NBC)    // 41472
#define NROW  (NUNIT*NPK)   // 414720
#define NSTEP (NPOS*NPK)    // 12960 per plane
#define SPITCH 161          // padded smem row stride (odd -> conflict-free)

// ---- static scratch (no allocations allowed) ----
__device__ float g_patches[(size_t)NROW * 49]; // [pos][bc][n][49]
__device__ float g_den[(size_t)NROW * 49];     // [pos][bc][n][49]
__device__ int   g_coords[NROW];               // x_i | (y_i<<8)
__device__ float g_Wc[49 * 52];                // Wp@Wb, padded to 52 cols
__device__ float g_bias[NPK * 49];             // (bp+pos_emb[n])@Wb + bb

// ============================================================
// K0: fold the two projections. Wc = Wp@Wb (fp64 accumulate),
// bias[n] = (bp + pos_emb[n])@Wb + bb.
// ============================================================
__global__ void prep_kernel(const float* __restrict__ Wp, const float* __restrict__ bp,
                            const float* __restrict__ pe, const float* __restrict__ Wb,
                            const float* __restrict__ bb) {
    int i = blockIdx.x * blockDim.x + threadIdx.x;
    if (i < 49 * 49) {
        int q = i / 49, k = i % 49;
        double s = 0.0;
        for (int e = 0; e < EMB; e++) s += (double)Wp[q * EMB + e] * (double)Wb[e * 49 + k];
        g_Wc[q * 52 + k] = (float)s;
    } else if (i < 49 * 49 + NPK * 49) {
        int j = i - 49 * 49;
        int n = j / 49, k = j % 49;
        double s = (double)bb[k];
        for (int e = 0; e < EMB; e++)
            s += ((double)bp[e] + (double)pe[n * EMB + e]) * (double)Wb[e * 49 + k];
        g_bias[j] = (float)s;
    } else if (i < 49 * 49 + NPK * 49 + 49 * 3) {
        int j = i - 49 * 49 - NPK * 49;
        g_Wc[(j / 3) * 52 + 49 + (j % 3)] = 0.0f;  // zero the pad columns
    }
}

// ============================================================
// K1: per (pos, bc): sims over 20x20 window, mask, top-10 with
// lax.top_k tie-break (lower flat index first), extract TRANSPOSED
// patches, emit the (swapped) reconstruction coords.
// One warp per unit, window staged in smem.
// ============================================================
__global__ void __launch_bounds__(128) simtopk_kernel(const float* __restrict__ images) {
    __shared__ float swin_all[4][400];
    int wid = threadIdx.x >> 5, lane = threadIdx.x & 31;
    int unit = blockIdx.x * 4 + wid;
    float* swin = swin_all[wid];

    int p  = unit >> 5;       // unit = p*32 + bc
    int bc = unit & 31;
    int px = p / NGRID, py = p % NGRID;
    int x = px * 4, y = py * 4;
    int xb0 = x - 7; if (xb0 < 0) xb0 = 0;
    int yb0 = y - 7; if (yb0 < 0) yb0 = 0;
    int winW = x + 13 - xb0;  // 13 / 17 / 20, upper edge never clips
    int winH = y + 13 - yb0;

    const float* plane = images + (size_t)bc * (HH * WW);
    for (int t = lane; t < 400; t += 32)
        swin[t] = plane[(yb0 + t / 20) * WW + xb0 + (t % 20)];
    __syncwarp();

    int ry = y - yb0, rx = x - xb0;   // ref lives inside the window
    int r = lane >> 1, ox0 = (lane & 1) * 7;
    bool active = lane < 28;
    float acc[7];
    int flatbase;
    if (active) {
        #pragma unroll
        for (int o = 0; o < 7; o++) acc[o] = 0.0f;
        for (int a = 0; a < 7; a++) {
            float w[13];
            #pragma unroll
            for (int v = 0; v < 13; v++) w[v] = swin[(r + a) * 20 + ox0 + v];
            #pragma unroll
            for (int b = 0; b < 7; b++) {
                float rv = swin[(ry + a) * 20 + rx + b];  // broadcast LDS
                #pragma unroll
                for (int o = 0; o < 7; o++) acc[o] = fmaf(w[o + b], rv, acc[o]);
            }
        }
        int maxr = winH - 7, maxc = winW - 7;
        #pragma unroll
        for (int o = 0; o < 7; o++)
            if (r > maxr || (ox0 + o) > maxc) acc[o] = -INFINITY;
        flatbase = r * LLEN + ox0;
    } else {
        #pragma unroll
        for (int o = 0; o < 7; o++) acc[o] = -INFINITY;
        flatbase = 1 << 20;
    }

    for (int n = 0; n < NPK; n++) {
        float bv = -INFINITY; int bi = 0x7fffffff;
        #pragma unroll
        for (int o = 0; o < 7; o++) {
            float v = acc[o]; int ii = flatbase + o;
            if (v > bv || (v == bv && ii < bi)) { bv = v; bi = ii; }
        }
        #pragma unroll
        for (int off = 16; off > 0; off >>= 1) {
            float ov = __shfl_xor_sync(0xffffffffu, bv, off);
            int   oi = __shfl_xor_sync(0xffffffffu, bi, off);
            if (ov > bv || (ov == bv && oi < bi)) { bv = ov; bi = oi; }
        }
        if (active && bi >= flatbase && bi < flatbase + 7) acc[bi - flatbase] = -INFINITY;

        int oy = bi / LLEN, ox = bi - oy * LLEN;
        float* pout = g_patches + ((size_t)unit * NPK + n) * 49;
        // patch[q] = win[oy + q%7][ox + q/7]  (transposed extraction)
        pout[lane] = swin[(oy + lane % 7) * 20 + ox + lane / 7];
        if (lane < 17) {
            int q = lane + 32;
            pout[q] = swin[(oy + q % 7) * 20 + ox + q / 7];
        }
        if (lane == 0)
            g_coords[unit * NPK + n] = (oy + xb0) | ((ox + yb0) << 8);  // x_i | y_i<<8 (bug kept)
    }
}

// ============================================================
// K2: den[row] = patches[row] @ Wc + bias[row % 10].
// Thread-per-row; Wc broadcast via vec4 smem loads.
// ============================================================
__global__ void __launch_bounds__(128) gemm_kernel() {
    __shared__ float s_pat[128 * 49];
    __shared__ float s_Wc[49 * 52];
    __shared__ float s_bias[NPK * 49];
    int t = threadIdx.x;
    size_t base = (size_t)blockIdx.x * 128 * 49;
    for (int i = t; i < 128 * 49; i += 128) s_pat[i] = g_patches[base + i];
    for (int i = t; i < 49 * 52;  i += 128) s_Wc[i]  = g_Wc[i];
    for (int i = t; i < NPK * 49; i += 128) s_bias[i] = g_bias[i];
    __syncthreads();

    int grow = blockIdx.x * 128 + t;
    int n = grow % NPK;
    float acc[52];
    #pragma unroll
    for (int k = 0; k < 52; k++) acc[k] = (k < 49) ? s_bias[n * 49 + k] : 0.0f;
    for (int q = 0; q < 49; q++) {
        float pq = s_pat[t * 49 + q];
        #pragma unroll
        for (int k4 = 0; k4 < 13; k4++) {
            float4 w = *(const float4*)&s_Wc[q * 52 + k4 * 4];
            acc[k4 * 4 + 0] = fmaf(pq, w.x, acc[k4 * 4 + 0]);
            acc[k4 * 4 + 1] = fmaf(pq, w.y, acc[k4 * 4 + 1]);
            acc[k4 * 4 + 2] = fmaf(pq, w.z, acc[k4 * 4 + 2]);
            acc[k4 * 4 + 3] = fmaf(pq, w.w, acc[k4 * 4 + 3]);
        }
    }
    __syncthreads();
    #pragma unroll
    for (int k = 0; k < 49; k++) s_pat[t * 49 + k] = acc[k];
    __syncthreads();
    for (int i = t; i < 128 * 49; i += 128) g_den[base + i] = s_pat[i];
}

// ============================================================
// K3: sequential reconstruction. One block per (b,c) plane,
// image + counter resident in smem. Per step t = pos*10 + n:
//   im[y+i][x+j] = (im*c + d)/(c+1) with c read pre-increment,
//   cn[x+i][y+j] += 1 (transposed slice — bug kept).
// Mid barrier only when the two 7x7 regions can overlap.
// ============================================================
__global__ void __launch_bounds__(64) recon_kernel(const float* __restrict__ images,
                                                   float* __restrict__ out) {
    extern __shared__ float sm[];
    float* s_im = sm;
    float* s_cn = sm + HH * SPITCH;
    int bc = blockIdx.x;
    int tid = threadIdx.x;

    const float* plane = images + (size_t)bc * (HH * WW);
    for (int t2 = tid; t2 < HH * WW; t2 += 64) {
        int rr = t2 / WW, cc = t2 % WW;
        s_im[rr * SPITCH + cc] = plane[t2];
        s_cn[rr * SPITCH + cc] = 1.0f;
    }
    __syncthreads();

    int row = tid / 7, col = tid % 7;
    bool act = tid < 49;

    // prefetch pipeline (depth 2): row index ridx(t) = (t/10)*320 + bc*10 + t%10
    int cA, cB; float dA = 0.0f, dB = 0.0f;
    {
        int r0 = bc * NPK;
        cA = g_coords[r0 + 0];
        cB = g_coords[r0 + 1];
        if (act) {
            dA = g_den[(size_t)(r0 + 0) * 49 + tid];
            dB = g_den[(size_t)(r0 + 1) * 49 + tid];
        }
    }

    for (int t = 0; t < NSTEP; t++) {
        int cC = 0; float dC = 0.0f;
        int tn = t + 2;
        if (tn < NSTEP) {
            int ri = (tn / NPK) * (NBC * NPK) + bc * NPK + (tn % NPK);
            cC = g_coords[ri];
            if (act) dC = g_den[(size_t)ri * 49 + tid];
        }

        int xi = cA & 0xFF, yi = (cA >> 8) & 0xFF;
        if (act) {
            int ia = (yi + row) * SPITCH + (xi + col);
            float c = s_cn[ia];
            float v = s_im[ia];
            s_im[ia] = (v * c + dA) / (c + 1.0f);
        }
        int dlt = xi - yi; if (dlt < 0) dlt = -dlt;
        if (dlt < 7) __syncthreads();     // read-region vs increment-region overlap
        if (act) s_cn[(xi + row) * SPITCH + (yi + col)] += 1.0f;
        __syncthreads();

        cA = cB; dA = dB; cB = cC; dB = dC;
    }

    __syncthreads();
    float* oplane = out + (size_t)bc * (HH * WW);
    for (int t2 = tid; t2 < HH * WW; t2 += 64) {
        int rr = t2 / WW, cc = t2 % WW;
        oplane[t2] = s_im[rr * SPITCH + cc];
    }
}

// ============================================================
extern "C" void kernel_launch(void* const* d_in, const int* in_sizes, int n_in,
                              void* d_out, int out_size) {
    const float* images = (const float*)d_in[0];
    const float* Wp = (const float*)d_in[1];
    const float* bp = (const float*)d_in[2];
    const float* pe = (const float*)d_in[3];
    const float* Wb = (const float*)d_in[4];
    const float* bb = (const float*)d_in[5];
    float* out = (float*)d_out;

    int prep_items = 49 * 49 + NPK * 49 + 49 * 3;
    prep_kernel<<<(prep_items + 127) / 128, 128>>>(Wp, bp, pe, Wb, bb);
    simtopk_kernel<<<NUNIT / 4, 128>>>(images);
    gemm_kernel<<<NROW / 128, 128>>>();

    size_t smem = (size_t)HH * SPITCH * 2 * sizeof(float);  // 206080 B
    cudaFuncSetAttribute(recon_kernel, cudaFuncAttributeMaxDynamicSharedMemorySize, (int)smem);
    recon_kernel<<<NBC, 64, smem>>>(images, out);
}

// round 3
// speedup vs baseline: 4.8259x; 4.8259x over previous
#include <cuda_runtime.h>
#include <math.h>

// ---- problem constants (fixed shapes) ----
#define NPK   10
#define LLEN  14
#define EMB   128
#define HH    160
#define WW    160
#define NBC   32            // B*C
#define NGRID 36
#define NPOS  (NGRID*NGRID) // 1296
#define NUNIT (NPOS*NBC)    // 41472
#define NROW  (NUNIT*NPK)   // 414720
#define PADCO (200 | (200<<9))  // never matches any pixel

// ---- static scratch ----
__device__ float g_patches[(size_t)NROW * 49];
__device__ float g_den[(size_t)NROW * 49];
__device__ int4  g_cpk4[NUNIT * 3];            // packed coords, stride 12 ints/unit
__device__ float g_Wc[49 * 52];
__device__ float g_bias[NPK * 49];

// ============================================================
// K0: fold projections. Wc = Wp@Wb, bias[n] = (bp+pos_emb[n])@Wb + bb
// ============================================================
__global__ void prep_kernel(const float* __restrict__ Wp, const float* __restrict__ bp,
                            const float* __restrict__ pe, const float* __restrict__ Wb,
                            const float* __restrict__ bb) {
    int i = blockIdx.x * blockDim.x + threadIdx.x;
    if (i < 49 * 49) {
        int q = i / 49, k = i % 49;
        double s = 0.0;
        for (int e = 0; e < EMB; e++) s += (double)Wp[q * EMB + e] * (double)Wb[e * 49 + k];
        g_Wc[q * 52 + k] = (float)s;
    } else if (i < 49 * 49 + NPK * 49) {
        int j = i - 49 * 49;
        int n = j / 49, k = j % 49;
        double s = (double)bb[k];
        for (int e = 0; e < EMB; e++)
            s += ((double)bp[e] + (double)pe[n * EMB + e]) * (double)Wb[e * 49 + k];
        g_bias[j] = (float)s;
    } else if (i < 49 * 49 + NPK * 49 + 49 * 3) {
        int j = i - 49 * 49 - NPK * 49;
        g_Wc[(j / 3) * 52 + 49 + (j % 3)] = 0.0f;
    }
}

// ============================================================
// K1: sims + top-10 (lax.top_k tie-break) + transposed patch
// extraction + packed coords (xi | yi<<9, stride 12, pads poisoned)
// ============================================================
__global__ void __launch_bounds__(128) simtopk_kernel(const float* __restrict__ images) {
    __shared__ float swin_all[4][400];
    int wid = threadIdx.x >> 5, lane = threadIdx.x & 31;
    int unit = blockIdx.x * 4 + wid;
    float* swin = swin_all[wid];

    int p  = unit >> 5;
    int bc = unit & 31;
    int px = p / NGRID, py = p % NGRID;
    int x = px * 4, y = py * 4;
    int xb0 = x - 7; if (xb0 < 0) xb0 = 0;
    int yb0 = y - 7; if (yb0 < 0) yb0 = 0;
    int winW = x + 13 - xb0;
    int winH = y + 13 - yb0;

    const float* plane = images + (size_t)bc * (HH * WW);
    for (int t = lane; t < 400; t += 32)
        swin[t] = plane[(yb0 + t / 20) * WW + xb0 + (t % 20)];
    __syncwarp();

    int ry = y - yb0, rx = x - xb0;
    int r = lane >> 1, ox0 = (lane & 1) * 7;
    bool active = lane < 28;
    float acc[7];
    int flatbase;
    if (active) {
        #pragma unroll
        for (int o = 0; o < 7; o++) acc[o] = 0.0f;
        for (int a = 0; a < 7; a++) {
            float w[13];
            #pragma unroll
            for (int v = 0; v < 13; v++) w[v] = swin[(r + a) * 20 + ox0 + v];
            #pragma unroll
            for (int b = 0; b < 7; b++) {
                float rv = swin[(ry + a) * 20 + rx + b];
                #pragma unroll
                for (int o = 0; o < 7; o++) acc[o] = fmaf(w[o + b], rv, acc[o]);
            }
        }
        int maxr = winH - 7, maxc = winW - 7;
        #pragma unroll
        for (int o = 0; o < 7; o++)
            if (r > maxr || (ox0 + o) > maxc) acc[o] = -INFINITY;
        flatbase = r * LLEN + ox0;
    } else {
        #pragma unroll
        for (int o = 0; o < 7; o++) acc[o] = -INFINITY;
        flatbase = 1 << 20;
    }

    int* gc = (int*)g_cpk4;
    for (int n = 0; n < NPK; n++) {
        float bv = -INFINITY; int bi = 0x7fffffff;
        #pragma unroll
        for (int o = 0; o < 7; o++) {
            float v = acc[o]; int ii = flatbase + o;
            if (v > bv || (v == bv && ii < bi)) { bv = v; bi = ii; }
        }
        #pragma unroll
        for (int off = 16; off > 0; off >>= 1) {
            float ov = __shfl_xor_sync(0xffffffffu, bv, off);
            int   oi = __shfl_xor_sync(0xffffffffu, bi, off);
            if (ov > bv || (ov == bv && oi < bi)) { bv = ov; bi = oi; }
        }
        if (active && bi >= flatbase && bi < flatbase + 7) acc[bi - flatbase] = -INFINITY;

        int oy = bi / LLEN, ox = bi - oy * LLEN;
        float* pout = g_patches + ((size_t)unit * NPK + n) * 49;
        pout[lane] = swin[(oy + lane % 7) * 20 + ox + lane / 7];
        if (lane < 17) {
            int q = lane + 32;
            pout[q] = swin[(oy + q % 7) * 20 + ox + q / 7];
        }
        if (lane == 0)
            gc[unit * 12 + n] = (oy + xb0) | ((ox + yb0) << 9);  // xi | yi<<9 (bug kept)
    }
    if (lane < 2) gc[unit * 12 + 10 + lane] = PADCO;
}

// ============================================================
// K2: den[row] = patches[row] @ Wc + bias[row % 10]
// ============================================================
__global__ void __launch_bounds__(128) gemm_kernel() {
    __shared__ float s_pat[128 * 49];
    __shared__ float s_Wc[49 * 52];
    __shared__ float s_bias[NPK * 49];
    int t = threadIdx.x;
    size_t base = (size_t)blockIdx.x * 128 * 49;
    for (int i = t; i < 128 * 49; i += 128) s_pat[i] = g_patches[base + i];
    for (int i = t; i < 49 * 52;  i += 128) s_Wc[i]  = g_Wc[i];
    for (int i = t; i < NPK * 49; i += 128) s_bias[i] = g_bias[i];
    __syncthreads();

    int grow = blockIdx.x * 128 + t;
    int n = grow % NPK;
    float acc[52];
    #pragma unroll
    for (int k = 0; k < 52; k++) acc[k] = (k < 49) ? s_bias[n * 49 + k] : 0.0f;
    for (int q = 0; q < 49; q++) {
        float pq = s_pat[t * 49 + q];
        #pragma unroll
        for (int k4 = 0; k4 < 13; k4++) {
            float4 w = *(const float4*)&s_Wc[q * 52 + k4 * 4];
            acc[k4 * 4 + 0] = fmaf(pq, w.x, acc[k4 * 4 + 0]);
            acc[k4 * 4 + 1] = fmaf(pq, w.y, acc[k4 * 4 + 1]);
            acc[k4 * 4 + 2] = fmaf(pq, w.z, acc[k4 * 4 + 2]);
            acc[k4 * 4 + 3] = fmaf(pq, w.w, acc[k4 * 4 + 3]);
        }
    }
    __syncthreads();
    #pragma unroll
    for (int k = 0; k < 49; k++) s_pat[t * 49 + k] = acc[k];
    __syncthreads();
    for (int i = t; i < 128 * 49; i += 128) g_den[base + i] = s_pat[i];
}

// ============================================================
// K3: per-pixel closed-form gather. Each pixel replays only its
// own read/inc events in ascending step order:
//   read : v <- (v*c + d) * 1/(c+1)   (c = counter before step)
//   inc  : c += 1  (at transposed slice -> roles of r/c swap)
// ============================================================
template<bool DR, bool DI>
__device__ __forceinline__ void proc_pos(const int4* __restrict__ cp, int sbase,
                                         int keyR, int keyI,
                                         float& v, int& cnt, float& fc, float& rc,
                                         const float* __restrict__ s_rcp) {
    #pragma unroll
    for (int g = 0; g < 3; g++) {
        int4 q = cp[g];
        int cs0 = q.x, cs1 = q.y, cs2 = q.z, cs3 = q.w;
        #pragma unroll
        for (int j = 0; j < 4; j++) {
            int n = g * 4 + j;
            if (n < 10) {
                int co = (j == 0) ? cs0 : (j == 1) ? cs1 : (j == 2) ? cs2 : cs3;
                if (DR) {
                    int rr = keyR - co;
                    if (((rr & 511) < 7) & (((unsigned)(rr >> 9)) < 7u)) {
                        float d = g_den[(size_t)(sbase + n) * 49 + (rr >> 9) * 7 + (rr & 511)];
                        v = (v * fc + d) * rc;
                    }
                }
                if (DI) {
                    int rr = keyI - co;
                    if (((rr & 511) < 7) & (((unsigned)(rr >> 9)) < 7u)) {
                        cnt++; fc += 1.0f; rc = s_rcp[cnt];
                    }
                }
            }
        }
    }
}

__global__ void __launch_bounds__(256) gather_kernel(const float* __restrict__ images,
                                                     float* __restrict__ out) {
    __shared__ float s_rcp[1024];
    int t = threadIdx.y * 32 + threadIdx.x;
    for (int i = t; i < 1024; i += 256) s_rcp[i] = __frcp_rn((float)(i + 1));
    __syncthreads();

    int c  = blockIdx.x * 32 + threadIdx.x;
    int r  = blockIdx.y * 8 + threadIdx.y;
    int bc = blockIdx.z;

    float v = images[((size_t)bc * HH + r) * WW + c];

    // candidate px ranges: xb0(px) in [t-19, t]
    int lr = (r <= 19) ? 0 : ((r - 9) >> 2);
    int hr = (r + 7) >> 2; if (hr > 35) hr = 35;
    int lc = (c <= 19) ? 0 : ((c - 9) >> 2);
    int hc = (c + 7) >> 2; if (hc > 35) hc = 35;

    int keyR = c | (r << 9);   // read: r-yi (hi), c-xi (lo)
    int keyI = r | (c << 9);   // inc : c-yi (hi), r-xi (lo)

    int cnt = 1; float fc = 1.0f, rc = 0.5f;

    int pmin = min(lr, lc), pmax = max(hr, hc);
    for (int px = pmin; px <= pmax; ++px) {
        bool pxR = (px >= lr) & (px <= hr);
        bool pxC = (px >= lc) & (px <= hc);
        if (!(pxR | pxC)) continue;
        for (int py = pmin; py <= pmax; ++py) {
            bool pyR = (py >= lr) & (py <= hr);
            bool pyC = (py >= lc) & (py <= hc);
            bool cr = pxC & pyR;   // this position can read pixel
            bool ci = pxR & pyC;   // this position can increment counter
            if (!(cr | ci)) continue;
            int pidx = (px * NGRID + py) * NBC + bc;
            const int4* cp = &g_cpk4[pidx * 3];
            int sbase = pidx * NPK;
            if (cr & ci)      proc_pos<true, true >(cp, sbase, keyR, keyI, v, cnt, fc, rc, s_rcp);
            else if (cr)      proc_pos<true, false>(cp, sbase, keyR, keyI, v, cnt, fc, rc, s_rcp);
            else              proc_pos<false, true>(cp, sbase, keyR, keyI, v, cnt, fc, rc, s_rcp);
        }
    }

    out[((size_t)bc * HH + r) * WW + c] = v;
}

// ============================================================
extern "C" void kernel_launch(void* const* d_in, const int* in_sizes, int n_in,
                              void* d_out, int out_size) {
    const float* images = (const float*)d_in[0];
    const float* Wp = (const float*)d_in[1];
    const float* bp = (const float*)d_in[2];
    const float* pe = (const float*)d_in[3];
    const float* Wb = (const float*)d_in[4];
    const float* bb = (const float*)d_in[5];
    float* out = (float*)d_out;

    int prep_items = 49 * 49 + NPK * 49 + 49 * 3;
    prep_kernel<<<(prep_items + 127) / 128, 128>>>(Wp, bp, pe, Wb, bb);
    simtopk_kernel<<<NUNIT / 4, 128>>>(images);
    gemm_kernel<<<NROW / 128, 128>>>();

    dim3 gg(WW / 32, HH / 8, NBC);
    dim3 bb2(32, 8);
    gather_kernel<<<gg, bb2>>>(images, out);
}

// round 4
// speedup vs baseline: 7.6299x; 1.5810x over previous
#include <cuda_runtime.h>
#include <math.h>

// ---- problem constants ----
#define NPK   10
#define LLEN  14
#define EMB   128
#define HH    160
#define WW    160
#define NBC   32
#define NGRID 36
#define NPOS  (NGRID*NGRID)
#define NUNIT (NPOS*NBC)    // 41472
#define NROW  (NUNIT*NPK)   // 414720
#define SEV   0x07070707

// ---- static scratch ----
__device__ float g_patches[(size_t)NROW * 49];
__device__ float g_den[(size_t)NROW * 49];
__device__ int4  g_cp[NUNIT * 2];   // [2u]=x-bytes(10+2 pad 0xC8), [2u+1]=y-bytes
__device__ float g_Wc[49 * 52];
__device__ float g_bias[NPK * 49];

// ============================================================
// K0: fold projections (fp32; error ~1e-6 << 1e-3 budget)
// ============================================================
__global__ void prep_kernel(const float* __restrict__ Wp, const float* __restrict__ bp,
                            const float* __restrict__ pe, const float* __restrict__ Wb,
                            const float* __restrict__ bb) {
    int i = blockIdx.x * blockDim.x + threadIdx.x;
    if (i < 49 * 49) {
        int q = i / 49, k = i % 49;
        float s = 0.0f;
        for (int e = 0; e < EMB; e++) s = fmaf(Wp[q * EMB + e], Wb[e * 49 + k], s);
        g_Wc[q * 52 + k] = s;
    } else if (i < 49 * 49 + NPK * 49) {
        int j = i - 49 * 49;
        int n = j / 49, k = j % 49;
        float s = bb[k];
        for (int e = 0; e < EMB; e++)
            s = fmaf(bp[e] + pe[n * EMB + e], Wb[e * 49 + k], s);
        g_bias[j] = s;
    } else if (i < 49 * 49 + NPK * 49 + 49 * 3) {
        int j = i - 49 * 49 - NPK * 49;
        g_Wc[(j / 3) * 52 + 49 + (j % 3)] = 0.0f;
    }
}

// ============================================================
// K1: sims + top-10 + transposed patches + byte-packed coords
// ============================================================
__global__ void __launch_bounds__(128) simtopk_kernel(const float* __restrict__ images) {
    __shared__ float swin_all[4][400];
    int wid = threadIdx.x >> 5, lane = threadIdx.x & 31;
    int unit = blockIdx.x * 4 + wid;
    float* swin = swin_all[wid];

    int p  = unit >> 5;
    int bc = unit & 31;
    int px = p / NGRID, py = p % NGRID;
    int x = px * 4, y = py * 4;
    int xb0 = x - 7; if (xb0 < 0) xb0 = 0;
    int yb0 = y - 7; if (yb0 < 0) yb0 = 0;
    int winW = x + 13 - xb0;
    int winH = y + 13 - yb0;

    const float* plane = images + (size_t)bc * (HH * WW);
    for (int t = lane; t < 400; t += 32)
        swin[t] = plane[(yb0 + t / 20) * WW + xb0 + (t % 20)];
    __syncwarp();

    int ry = y - yb0, rx = x - xb0;
    int r = lane >> 1, ox0 = (lane & 1) * 7;
    bool active = lane < 28;
    float acc[7];
    int flatbase;
    if (active) {
        #pragma unroll
        for (int o = 0; o < 7; o++) acc[o] = 0.0f;
        for (int a = 0; a < 7; a++) {
            float w[13];
            #pragma unroll
            for (int v = 0; v < 13; v++) w[v] = swin[(r + a) * 20 + ox0 + v];
            #pragma unroll
            for (int b = 0; b < 7; b++) {
                float rv = swin[(ry + a) * 20 + rx + b];
                #pragma unroll
                for (int o = 0; o < 7; o++) acc[o] = fmaf(w[o + b], rv, acc[o]);
            }
        }
        int maxr = winH - 7, maxc = winW - 7;
        #pragma unroll
        for (int o = 0; o < 7; o++)
            if (r > maxr || (ox0 + o) > maxc) acc[o] = -INFINITY;
        flatbase = r * LLEN + ox0;
    } else {
        #pragma unroll
        for (int o = 0; o < 7; o++) acc[o] = -INFINITY;
        flatbase = 1 << 20;
    }

    int xw0 = 0, xw1 = 0, xw2 = 0xC8C80000, yw0 = 0, yw1 = 0, yw2 = 0xC8C80000;

    for (int n = 0; n < NPK; n++) {
        float bv = -INFINITY; int bi = 0x7fffffff;
        #pragma unroll
        for (int o = 0; o < 7; o++) {
            float v = acc[o]; int ii = flatbase + o;
            if (v > bv || (v == bv && ii < bi)) { bv = v; bi = ii; }
        }
        #pragma unroll
        for (int off = 16; off > 0; off >>= 1) {
            float ov = __shfl_xor_sync(0xffffffffu, bv, off);
            int   oi = __shfl_xor_sync(0xffffffffu, bi, off);
            if (ov > bv || (ov == bv && oi < bi)) { bv = ov; bi = oi; }
        }
        if (active && bi >= flatbase && bi < flatbase + 7) acc[bi - flatbase] = -INFINITY;

        int oy = bi / LLEN, ox = bi - oy * LLEN;
        float* pout = g_patches + ((size_t)unit * NPK + n) * 49;
        pout[lane] = swin[(oy + lane % 7) * 20 + ox + lane / 7];
        if (lane < 17) {
            int q = lane + 32;
            pout[q] = swin[(oy + q % 7) * 20 + ox + q / 7];
        }
        if (lane == 0) {
            int xb = oy + xb0, yb = ox + yb0;   // bug kept: x from row off, y from col off
            int sh = (n & 3) * 8;
            if (n < 4)      { xw0 |= xb << sh; yw0 |= yb << sh; }
            else if (n < 8) { xw1 |= xb << sh; yw1 |= yb << sh; }
            else            { xw2 |= xb << sh; yw2 |= yb << sh; }
        }
    }
    if (lane == 0) {
        g_cp[unit * 2]     = make_int4(xw0, xw1, xw2, 0);
        g_cp[unit * 2 + 1] = make_int4(yw0, yw1, yw2, 0);
    }
}

// ============================================================
// K2: den[row] = patches[row] @ Wc + bias[row % 10]
// ============================================================
__global__ void __launch_bounds__(128) gemm_kernel() {
    __shared__ float s_pat[128 * 49];
    __shared__ float s_Wc[49 * 52];
    __shared__ float s_bias[NPK * 49];
    int t = threadIdx.x;
    size_t base = (size_t)blockIdx.x * 128 * 49;
    for (int i = t; i < 128 * 49; i += 128) s_pat[i] = g_patches[base + i];
    for (int i = t; i < 49 * 52;  i += 128) s_Wc[i]  = g_Wc[i];
    for (int i = t; i < NPK * 49; i += 128) s_bias[i] = g_bias[i];
    __syncthreads();

    int grow = blockIdx.x * 128 + t;
    int n = grow % NPK;
    float acc[52];
    #pragma unroll
    for (int k = 0; k < 52; k++) acc[k] = (k < 49) ? s_bias[n * 49 + k] : 0.0f;
    for (int q = 0; q < 49; q++) {
        float pq = s_pat[t * 49 + q];
        #pragma unroll
        for (int k4 = 0; k4 < 13; k4++) {
            float4 w = *(const float4*)&s_Wc[q * 52 + k4 * 4];
            acc[k4 * 4 + 0] = fmaf(pq, w.x, acc[k4 * 4 + 0]);
            acc[k4 * 4 + 1] = fmaf(pq, w.y, acc[k4 * 4 + 1]);
            acc[k4 * 4 + 2] = fmaf(pq, w.z, acc[k4 * 4 + 2]);
            acc[k4 * 4 + 3] = fmaf(pq, w.w, acc[k4 * 4 + 3]);
        }
    }
    __syncthreads();
    #pragma unroll
    for (int k = 0; k < 49; k++) s_pat[t * 49 + k] = acc[k];
    __syncthreads();
    for (int i = t; i < 128 * 49; i += 128) g_den[base + i] = s_pat[i];
}

// ============================================================
// K3: per-pixel gather, class-split by event ordering.
// reads: xi in (c-7,c], yi in (r-7,r]  (px in Rc, py in Rr)
// incs : xi in (r-7,r], yi in (c-7,c]  (px in Rr, py in Rc)
// ============================================================
__device__ __forceinline__ void read_word(int xw, int yw, int n0, int sbase,
                                          int cvec, int rvec, float fc, float rc,
                                          float& v) {
    int xd = __vsub4(cvec, xw), yd = __vsub4(rvec, yw);
    unsigned m = __vcmpltu4(xd, SEV) & __vcmpltu4(yd, SEV);
    while (m) {
        int sh = __ffs(m) - 1;                 // multiple of 8
        int n = n0 + (sh >> 3);
        int didx = ((yd >> sh) & 7) * 7 + ((xd >> sh) & 7);
        float d = g_den[(size_t)(sbase + n) * 49 + didx];
        v = fmaf(v, fc, d) * rc;
        m &= ~(0xFFu << sh);
    }
}

__device__ __forceinline__ int inc_count_word(int xw, int yw, int cvec, int rvec) {
    unsigned m = __vcmpltu4(__vsub4(rvec, xw), SEV) &
                 __vcmpltu4(__vsub4(cvec, yw), SEV);
    return __popc(m & 0x01010101u);
}

__device__ __forceinline__ void mixed_word(int xw, int yw, int n0, int sbase,
                                           int cvec, int rvec,
                                           float& v, int& cnt, float& fc, float& rc,
                                           const float* __restrict__ s_rcp) {
    int xdR = __vsub4(cvec, xw), ydR = __vsub4(rvec, yw);
    int xdI = __vsub4(rvec, xw), ydI = __vsub4(cvec, yw);
    unsigned mR = __vcmpltu4(xdR, SEV) & __vcmpltu4(ydR, SEV);
    unsigned mI = __vcmpltu4(xdI, SEV) & __vcmpltu4(ydI, SEV);
    unsigned mo = mR | mI;
    while (mo) {
        int sh = __ffs(mo) - 1;
        if ((mR >> sh) & 1) {
            int n = n0 + (sh >> 3);
            int didx = ((ydR >> sh) & 7) * 7 + ((xdR >> sh) & 7);
            float d = g_den[(size_t)(sbase + n) * 49 + didx];
            v = fmaf(v, fc, d) * rc;
        }
        if ((mI >> sh) & 1) { cnt++; fc += 1.0f; rc = s_rcp[cnt]; }
        mo &= ~(0xFFu << sh);
    }
}

__device__ __forceinline__ void read_pos(int pidx, int cvec, int rvec,
                                         float fc, float rc, float& v) {
    int4 xq = g_cp[pidx * 2];
    int4 yq = g_cp[pidx * 2 + 1];
    int sbase = pidx * NPK;
    read_word(xq.x, yq.x, 0, sbase, cvec, rvec, fc, rc, v);
    read_word(xq.y, yq.y, 4, sbase, cvec, rvec, fc, rc, v);
    read_word(xq.z, yq.z, 8, sbase, cvec, rvec, fc, rc, v);
}

__device__ __forceinline__ int inc_pos(int pidx, int cvec, int rvec) {
    int4 xq = g_cp[pidx * 2];
    int4 yq = g_cp[pidx * 2 + 1];
    return inc_count_word(xq.x, yq.x, cvec, rvec) +
           inc_count_word(xq.y, yq.y, cvec, rvec) +
           inc_count_word(xq.z, yq.z, cvec, rvec);
}

__device__ __forceinline__ void mixed_pos(int pidx, int cvec, int rvec,
                                          float& v, int& cnt, float& fc, float& rc,
                                          const float* __restrict__ s_rcp) {
    int4 xq = g_cp[pidx * 2];
    int4 yq = g_cp[pidx * 2 + 1];
    int sbase = pidx * NPK;
    mixed_word(xq.x, yq.x, 0, sbase, cvec, rvec, v, cnt, fc, rc, s_rcp);
    mixed_word(xq.y, yq.y, 4, sbase, cvec, rvec, v, cnt, fc, rc, s_rcp);
    mixed_word(xq.z, yq.z, 8, sbase, cvec, rvec, v, cnt, fc, rc, s_rcp);
}

__global__ void __launch_bounds__(256) gather_kernel(const float* __restrict__ images,
                                                     float* __restrict__ out) {
    __shared__ float s_rcp[512];
    {
        int t = threadIdx.y * 32 + threadIdx.x;
        for (int i = t; i < 512; i += 256) s_rcp[i] = __frcp_rn((float)(i + 1));
    }
    __syncthreads();

    int c  = blockIdx.x * 32 + threadIdx.x;
    int r  = blockIdx.y * 8 + threadIdx.y;
    int bc = blockIdx.z;

    float v = images[((size_t)bc * HH + r) * WW + c];

    int lr = (r <= 19) ? 0 : ((r - 9) >> 2);
    int hr = (r + 7) >> 2; if (hr > 35) hr = 35;
    int lc = (c <= 19) ? 0 : ((c - 9) >> 2);
    int hc = (c + 7) >> 2; if (hc > 35) hc = 35;

    if (lr <= hr && lc <= hc) {
        int cvec = c * 0x01010101, rvec = r * 0x01010101;

        if (hc < lr) {
            // all reads before all incs: counter stays 1
            for (int px = lc; px <= hc; ++px) {
                int pbase = (px * NGRID + lr) * NBC + bc;
                for (int py = lr; py <= hr; ++py, pbase += NBC)
                    read_pos(pbase, cvec, rvec, 1.0f, 0.5f, v);
            }
        } else if (hr < lc) {
            // all incs before all reads: count once, constant c
            int I = 0;
            for (int px = lr; px <= hr; ++px) {
                int pbase = (px * NGRID + lc) * NBC + bc;
                for (int py = lc; py <= hc; ++py, pbase += NBC)
                    I += inc_pos(pbase, cvec, rvec);
            }
            float fc = (float)(1 + I);
            float rc = s_rcp[1 + I];
            for (int px = lc; px <= hc; ++px) {
                int pbase = (px * NGRID + lr) * NBC + bc;
                for (int py = lr; py <= hr; ++py, pbase += NBC)
                    read_pos(pbase, cvec, rvec, fc, rc, v);
            }
        } else {
            // general merged walk in step order
            int cnt = 1; float fc = 1.0f, rc = 0.5f;
            int pmin = min(lr, lc), pmax = max(hr, hc);
            for (int px = pmin; px <= pmax; ++px) {
                bool cR = (px >= lc) & (px <= hc);
                bool cI = (px >= lr) & (px <= hr);
                if (cR & cI) {
                    int pbase = (px * NGRID + pmin) * NBC + bc;
                    for (int py = pmin; py <= pmax; ++py, pbase += NBC) {
                        bool pR = (py >= lr) & (py <= hr);
                        bool pC = (py >= lc) & (py <= hc);
                        if (pR & pC)      mixed_pos(pbase, cvec, rvec, v, cnt, fc, rc, s_rcp);
                        else if (pR)      read_pos(pbase, cvec, rvec, fc, rc, v);
                        else if (pC) {
                            int k = inc_pos(pbase, cvec, rvec);
                            cnt += k; fc += (float)k; rc = s_rcp[cnt];
                        }
                    }
                } else if (cR) {
                    int pbase = (px * NGRID + lr) * NBC + bc;
                    for (int py = lr; py <= hr; ++py, pbase += NBC)
                        read_pos(pbase, cvec, rvec, fc, rc, v);
                } else if (cI) {
                    int k = 0;
                    int pbase = (px * NGRID + lc) * NBC + bc;
                    for (int py = lc; py <= hc; ++py, pbase += NBC)
                        k += inc_pos(pbase, cvec, rvec);
                    cnt += k; fc += (float)k; rc = s_rcp[cnt];
                }
            }
        }
    }

    out[((size_t)bc * HH + r) * WW + c] = v;
}

// ============================================================
extern "C" void kernel_launch(void* const* d_in, const int* in_sizes, int n_in,
                              void* d_out, int out_size) {
    const float* images = (const float*)d_in[0];
    const float* Wp = (const float*)d_in[1];
    const float* bp = (const float*)d_in[2];
    const float* pe = (const float*)d_in[3];
    const float* Wb = (const float*)d_in[4];
    const float* bb = (const float*)d_in[5];
    float* out = (float*)d_out;

    int prep_items = 49 * 49 + NPK * 49 + 49 * 3;
    prep_kernel<<<(prep_items + 127) / 128, 128>>>(Wp, bp, pe, Wb, bb);
    simtopk_kernel<<<NUNIT / 4, 128>>>(images);
    gemm_kernel<<<NROW / 128, 128>>>();

    dim3 gg(WW / 32, HH / 8, NBC);
    dim3 bl(32, 8);
    gather_kernel<<<gg, bl>>>(images, out);
}

// round 5
// speedup vs baseline: 9.9111x; 1.2990x over previous
#include <cuda_runtime.h>
#include <math.h>

// ---- problem constants ----
#define NPK   10
#define LLEN  14
#define EMB   128
#define HH    160
#define WW    160
#define NBC   32
#define NGRID 36
#define NPOS  (NGRID*NGRID)
#define NUNIT (NPOS*NBC)    // 41472
#define NROW  (NUNIT*NPK)   // 414720
#define SEV   0x07070707

// ---- static scratch ----
__device__ float g_patches[(size_t)NROW * 49];
__device__ float g_den[(size_t)NROW * 49];
__device__ int4  g_cp[NUNIT * 2];   // [2u]=x-bytes(10+2 pad 0xC8), [2u+1]=y-bytes
__device__ float g_Wc[49 * 52];
__device__ float g_bias[NPK * 49];

// ============================================================
// K0: fold projections
// ============================================================
__global__ void prep_kernel(const float* __restrict__ Wp, const float* __restrict__ bp,
                            const float* __restrict__ pe, const float* __restrict__ Wb,
                            const float* __restrict__ bb) {
    int i = blockIdx.x * blockDim.x + threadIdx.x;
    if (i < 49 * 49) {
        int q = i / 49, k = i % 49;
        float s = 0.0f;
        for (int e = 0; e < EMB; e++) s = fmaf(Wp[q * EMB + e], Wb[e * 49 + k], s);
        g_Wc[q * 52 + k] = s;
    } else if (i < 49 * 49 + NPK * 49) {
        int j = i - 49 * 49;
        int n = j / 49, k = j % 49;
        float s = bb[k];
        for (int e = 0; e < EMB; e++)
            s = fmaf(bp[e] + pe[n * EMB + e], Wb[e * 49 + k], s);
        g_bias[j] = s;
    } else if (i < 49 * 49 + NPK * 49 + 49 * 3) {
        int j = i - 49 * 49 - NPK * 49;
        g_Wc[(j / 3) * 52 + 49 + (j % 3)] = 0.0f;
    }
}

// ============================================================
// K1: sims + top-10 + transposed patches + byte-packed coords
// ============================================================
__global__ void __launch_bounds__(128) simtopk_kernel(const float* __restrict__ images) {
    __shared__ float swin_all[4][400];
    int wid = threadIdx.x >> 5, lane = threadIdx.x & 31;
    int unit = blockIdx.x * 4 + wid;
    float* swin = swin_all[wid];

    int p  = unit >> 5;
    int bc = unit & 31;
    int px = p / NGRID, py = p % NGRID;
    int x = px * 4, y = py * 4;
    int xb0 = x - 7; if (xb0 < 0) xb0 = 0;
    int yb0 = y - 7; if (yb0 < 0) yb0 = 0;
    int winW = x + 13 - xb0;
    int winH = y + 13 - yb0;

    const float* plane = images + (size_t)bc * (HH * WW);
    for (int t = lane; t < 400; t += 32)
        swin[t] = plane[(yb0 + t / 20) * WW + xb0 + (t % 20)];
    __syncwarp();

    int ry = y - yb0, rx = x - xb0;
    int r = lane >> 1, ox0 = (lane & 1) * 7;
    bool active = lane < 28;
    float acc[7];
    int flatbase;
    if (active) {
        #pragma unroll
        for (int o = 0; o < 7; o++) acc[o] = 0.0f;
        for (int a = 0; a < 7; a++) {
            float w[13];
            #pragma unroll
            for (int v = 0; v < 13; v++) w[v] = swin[(r + a) * 20 + ox0 + v];
            #pragma unroll
            for (int b = 0; b < 7; b++) {
                float rv = swin[(ry + a) * 20 + rx + b];
                #pragma unroll
                for (int o = 0; o < 7; o++) acc[o] = fmaf(w[o + b], rv, acc[o]);
            }
        }
        int maxr = winH - 7, maxc = winW - 7;
        #pragma unroll
        for (int o = 0; o < 7; o++)
            if (r > maxr || (ox0 + o) > maxc) acc[o] = -INFINITY;
        flatbase = r * LLEN + ox0;
    } else {
        #pragma unroll
        for (int o = 0; o < 7; o++) acc[o] = -INFINITY;
        flatbase = 1 << 20;
    }

    int xw0 = 0, xw1 = 0, xw2 = 0xC8C80000, yw0 = 0, yw1 = 0, yw2 = 0xC8C80000;

    for (int n = 0; n < NPK; n++) {
        float bv = -INFINITY; int bi = 0x7fffffff;
        #pragma unroll
        for (int o = 0; o < 7; o++) {
            float v = acc[o]; int ii = flatbase + o;
            if (v > bv || (v == bv && ii < bi)) { bv = v; bi = ii; }
        }
        #pragma unroll
        for (int off = 16; off > 0; off >>= 1) {
            float ov = __shfl_xor_sync(0xffffffffu, bv, off);
            int   oi = __shfl_xor_sync(0xffffffffu, bi, off);
            if (ov > bv || (ov == bv && oi < bi)) { bv = ov; bi = oi; }
        }
        if (active && bi >= flatbase && bi < flatbase + 7) acc[bi - flatbase] = -INFINITY;

        int oy = bi / LLEN, ox = bi - oy * LLEN;
        float* pout = g_patches + ((size_t)unit * NPK + n) * 49;
        pout[lane] = swin[(oy + lane % 7) * 20 + ox + lane / 7];
        if (lane < 17) {
            int q = lane + 32;
            pout[q] = swin[(oy + q % 7) * 20 + ox + q / 7];
        }
        if (lane == 0) {
            int xb = oy + xb0, yb = ox + yb0;   // bug kept: x from row off, y from col off
            int sh = (n & 3) * 8;
            if (n < 4)      { xw0 |= xb << sh; yw0 |= yb << sh; }
            else if (n < 8) { xw1 |= xb << sh; yw1 |= yb << sh; }
            else            { xw2 |= xb << sh; yw2 |= yb << sh; }
        }
    }
    if (lane == 0) {
        g_cp[unit * 2]     = make_int4(xw0, xw1, xw2, 0);
        g_cp[unit * 2 + 1] = make_int4(yw0, yw1, yw2, 0);
    }
}

// ============================================================
// K2: den[row] = patches[row] @ Wc + bias[row % 10]
// ============================================================
__global__ void __launch_bounds__(128) gemm_kernel() {
    __shared__ float s_pat[128 * 49];
    __shared__ float s_Wc[49 * 52];
    __shared__ float s_bias[NPK * 49];
    int t = threadIdx.x;
    size_t base = (size_t)blockIdx.x * 128 * 49;
    for (int i = t; i < 128 * 49; i += 128) s_pat[i] = g_patches[base + i];
    for (int i = t; i < 49 * 52;  i += 128) s_Wc[i]  = g_Wc[i];
    for (int i = t; i < NPK * 49; i += 128) s_bias[i] = g_bias[i];
    __syncthreads();

    int grow = blockIdx.x * 128 + t;
    int n = grow % NPK;
    float acc[52];
    #pragma unroll
    for (int k = 0; k < 52; k++) acc[k] = (k < 49) ? s_bias[n * 49 + k] : 0.0f;
    for (int q = 0; q < 49; q++) {
        float pq = s_pat[t * 49 + q];
        #pragma unroll
        for (int k4 = 0; k4 < 13; k4++) {
            float4 w = *(const float4*)&s_Wc[q * 52 + k4 * 4];
            acc[k4 * 4 + 0] = fmaf(pq, w.x, acc[k4 * 4 + 0]);
            acc[k4 * 4 + 1] = fmaf(pq, w.y, acc[k4 * 4 + 1]);
            acc[k4 * 4 + 2] = fmaf(pq, w.z, acc[k4 * 4 + 2]);
            acc[k4 * 4 + 3] = fmaf(pq, w.w, acc[k4 * 4 + 3]);
        }
    }
    __syncthreads();
    #pragma unroll
    for (int k = 0; k < 49; k++) s_pat[t * 49 + k] = acc[k];
    __syncthreads();
    for (int i = t; i < 128 * 49; i += 128) g_den[base + i] = s_pat[i];
}

// ============================================================
// K3: per-pixel gather, lanes = bc planes (warp-uniform control).
// reads: xi in (c-7,c], yi in (r-7,r]
// incs : xi in (r-7,r], yi in (c-7,c]   (transposed-counter bug)
// ============================================================
__device__ __forceinline__ void read_word(int xw, int yw, int n0, int sbase,
                                          int cvec, int rvec, float fc, float rc,
                                          float& v) {
    int xd = __vsub4(cvec, xw), yd = __vsub4(rvec, yw);
    unsigned m = __vcmpltu4(xd, SEV) & __vcmpltu4(yd, SEV);
    while (m) {
        int sh = __ffs(m) - 1;
        int n = n0 + (sh >> 3);
        int didx = ((yd >> sh) & 7) * 7 + ((xd >> sh) & 7);
        float d = g_den[(size_t)(sbase + n) * 49 + didx];
        v = fmaf(v, fc, d) * rc;
        m &= ~(0xFFu << sh);
    }
}

__device__ __forceinline__ int inc_count_word(int xw, int yw, int cvec, int rvec) {
    unsigned m = __vcmpltu4(__vsub4(rvec, xw), SEV) &
                 __vcmpltu4(__vsub4(cvec, yw), SEV);
    return __popc(m & 0x01010101u);
}

__device__ __forceinline__ void mixed_word(int xw, int yw, int n0, int sbase,
                                           int cvec, int rvec,
                                           float& v, int& cnt, float& fc, float& rc,
                                           const float* __restrict__ s_rcp) {
    int xdR = __vsub4(cvec, xw), ydR = __vsub4(rvec, yw);
    int xdI = __vsub4(rvec, xw), ydI = __vsub4(cvec, yw);
    unsigned mR = __vcmpltu4(xdR, SEV) & __vcmpltu4(ydR, SEV);
    unsigned mI = __vcmpltu4(xdI, SEV) & __vcmpltu4(ydI, SEV);
    unsigned mo = mR | mI;
    while (mo) {
        int sh = __ffs(mo) - 1;
        if ((mR >> sh) & 1) {
            int n = n0 + (sh >> 3);
            int didx = ((ydR >> sh) & 7) * 7 + ((xdR >> sh) & 7);
            float d = g_den[(size_t)(sbase + n) * 49 + didx];
            v = fmaf(v, fc, d) * rc;
        }
        if ((mI >> sh) & 1) { cnt++; fc += 1.0f; rc = s_rcp[cnt]; }
        mo &= ~(0xFFu << sh);
    }
}

__device__ __forceinline__ void read_pos(int pidx, int cvec, int rvec,
                                         float fc, float rc, float& v) {
    int4 xq = g_cp[pidx * 2];
    int4 yq = g_cp[pidx * 2 + 1];
    int sbase = pidx * NPK;
    read_word(xq.x, yq.x, 0, sbase, cvec, rvec, fc, rc, v);
    read_word(xq.y, yq.y, 4, sbase, cvec, rvec, fc, rc, v);
    read_word(xq.z, yq.z, 8, sbase, cvec, rvec, fc, rc, v);
}

__device__ __forceinline__ int inc_pos(int pidx, int cvec, int rvec) {
    int4 xq = g_cp[pidx * 2];
    int4 yq = g_cp[pidx * 2 + 1];
    return inc_count_word(xq.x, yq.x, cvec, rvec) +
           inc_count_word(xq.y, yq.y, cvec, rvec) +
           inc_count_word(xq.z, yq.z, cvec, rvec);
}

__device__ __forceinline__ void mixed_pos(int pidx, int cvec, int rvec,
                                          float& v, int& cnt, float& fc, float& rc,
                                          const float* __restrict__ s_rcp) {
    int4 xq = g_cp[pidx * 2];
    int4 yq = g_cp[pidx * 2 + 1];
    int sbase = pidx * NPK;
    mixed_word(xq.x, yq.x, 0, sbase, cvec, rvec, v, cnt, fc, rc, s_rcp);
    mixed_word(xq.y, yq.y, 4, sbase, cvec, rvec, v, cnt, fc, rc, s_rcp);
    mixed_word(xq.z, yq.z, 8, sbase, cvec, rvec, v, cnt, fc, rc, s_rcp);
}

__global__ void __launch_bounds__(256) gather_kernel(const float* __restrict__ images,
                                                     float* __restrict__ out) {
    __shared__ float s_rcp[512];
    {
        int t = threadIdx.y * 32 + threadIdx.x;
        for (int i = t; i < 512; i += 256) s_rcp[i] = __frcp_rn((float)(i + 1));
    }
    __syncthreads();

    int bc  = threadIdx.x;                       // lane = plane -> uniform (r,c) per warp
    int pix = blockIdx.x * 8 + threadIdx.y;
    int r = pix / WW, c = pix % WW;

    float v = images[(size_t)bc * (HH * WW) + pix];

    int lr = (r <= 19) ? 0 : ((r - 9) >> 2);
    int hr = (r + 7) >> 2; if (hr > 35) hr = 35;
    int lc = (c <= 19) ? 0 : ((c - 9) >> 2);
    int hc = (c + 7) >> 2; if (hc > 35) hc = 35;

    if (lr <= hr && lc <= hc) {
        int cvec = c * 0x01010101, rvec = r * 0x01010101;

        if (hc < lr) {
            // all reads before all incs: counter stays 1
            for (int px = lc; px <= hc; ++px) {
                int pbase = (px * NGRID + lr) * NBC + bc;
                for (int py = lr; py <= hr; ++py, pbase += NBC)
                    read_pos(pbase, cvec, rvec, 1.0f, 0.5f, v);
            }
        } else if (hr < lc) {
            // all incs before all reads: count once, constant c
            int I = 0;
            for (int px = lr; px <= hr; ++px) {
                int pbase = (px * NGRID + lc) * NBC + bc;
                for (int py = lc; py <= hc; ++py, pbase += NBC)
                    I += inc_pos(pbase, cvec, rvec);
            }
            float fc = (float)(1 + I);
            float rc = s_rcp[1 + I];
            for (int px = lc; px <= hc; ++px) {
                int pbase = (px * NGRID + lr) * NBC + bc;
                for (int py = lr; py <= hr; ++py, pbase += NBC)
                    read_pos(pbase, cvec, rvec, fc, rc, v);
            }
        } else {
            // general merged walk in step order
            int cnt = 1; float fc = 1.0f, rc = 0.5f;
            int pmin = min(lr, lc), pmax = max(hr, hc);
            for (int px = pmin; px <= pmax; ++px) {
                bool cR = (px >= lc) & (px <= hc);
                bool cI = (px >= lr) & (px <= hr);
                if (cR & cI) {
                    int pbase = (px * NGRID + pmin) * NBC + bc;
                    for (int py = pmin; py <= pmax; ++py, pbase += NBC) {
                        bool pR = (py >= lr) & (py <= hr);
                        bool pC = (py >= lc) & (py <= hc);
                        if (pR & pC)      mixed_pos(pbase, cvec, rvec, v, cnt, fc, rc, s_rcp);
                        else if (pR)      read_pos(pbase, cvec, rvec, fc, rc, v);
                        else if (pC) {
                            int k = inc_pos(pbase, cvec, rvec);
                            cnt += k; fc += (float)k; rc = s_rcp[cnt];
                        }
                    }
                } else if (cR) {
                    int pbase = (px * NGRID + lr) * NBC + bc;
                    for (int py = lr; py <= hr; ++py, pbase += NBC)
                        read_pos(pbase, cvec, rvec, fc, rc, v);
                } else if (cI) {
                    int k = 0;
                    int pbase = (px * NGRID + lc) * NBC + bc;
                    for (int py = lc; py <= hc; ++py, pbase += NBC)
                        k += inc_pos(pbase, cvec, rvec);
                    cnt += k; fc += (float)k; rc = s_rcp[cnt];
                }
            }
        }
    }

    out[(size_t)bc * (HH * WW) + pix] = v;
}

// ============================================================
extern "C" void kernel_launch(void* const* d_in, const int* in_sizes, int n_in,
                              void* d_out, int out_size) {
    const float* images = (const float*)d_in[0];
    const float* Wp = (const float*)d_in[1];
    const float* bp = (const float*)d_in[2];
    const float* pe = (const float*)d_in[3];
    const float* Wb = (const float*)d_in[4];
    const float* bb = (const float*)d_in[5];
    float* out = (float*)d_out;

    int prep_items = 49 * 49 + NPK * 49 + 49 * 3;
    prep_kernel<<<(prep_items + 127) / 128, 128>>>(Wp, bp, pe, Wb, bb);
    simtopk_kernel<<<NUNIT / 4, 128>>>(images);
    gemm_kernel<<<NROW / 128, 128>>>();

    dim3 gg((HH * WW) / 8);
    dim3 bl(32, 8);
    gather_kernel<<<gg, bl>>>(images, out);
}